// round 4
// baseline (speedup 1.0000x reference)
#include <cuda_runtime.h>
#include <cuda_bf16.h>

// PathRaster2d: quadratic Bezier (3 cps) on 2048x2048.
// R4: 256x64 tiles (256 blocks), warp-autonomous, 256-bit stores
// (st.global.v8.f32, Blackwell). Each thread owns 8 contiguous floats (32B)
// in 8 rows -> 8 STG.256. Exact point-to-box prune per warp (ballot); active
// warps (rare) run the full per-pixel min loop with reference-matched fp32
// rounding (bit-identical to prior rounds, rel_err 0.0).

#define CANVAS_H 2048
#define CANVAS_W 2048
#define TILE_W 256
#define TILE_H 64
#define ROWS_PER_THREAD 8
#define ROW_STRIDE 8            // ty in [0,8), rows ty + 8r

__device__ __forceinline__ void stg256(float* p, const float* v)
{
    asm volatile("st.global.v8.f32 [%0], {%1,%2,%3,%4,%5,%6,%7,%8};"
                 :: "l"(p), "f"(v[0]), "f"(v[1]), "f"(v[2]), "f"(v[3]),
                    "f"(v[4]), "f"(v[5]), "f"(v[6]), "f"(v[7])
                 : "memory");
}

__global__ void __launch_bounds__(256)
path_raster_kernel(const float* __restrict__ kp, float* __restrict__ out)
{
    const int tx = threadIdx.x;          // 0..31 (lane == sample index)
    const int ty = threadIdx.y;          // 0..7
    const int x0 = blockIdx.x * TILE_W;
    const int y0 = blockIdx.y * TILE_H;

    // ---- per-lane sample (lane i computes sample i), ref-matched rounding ----
    // t_i = i * fl(1/31), endpoint forced to 1.0 (matches jnp.linspace)
    float t = (tx == 31) ? 1.0f : (float)tx * (1.0f / 31.0f);
    float u = __fsub_rn(1.0f, t);
    float b0 = __fmul_rn(u, u);
    float b1 = __fmul_rn(__fmul_rn(2.0f, t), u);
    float b2 = __fmul_rn(t, t);
    float ky0 = __fmul_rn(__ldg(kp + 0), 2048.0f), kx0 = __fmul_rn(__ldg(kp + 1), 2048.0f);
    float ky1 = __fmul_rn(__ldg(kp + 2), 2048.0f), kx1 = __fmul_rn(__ldg(kp + 3), 2048.0f);
    float ky2 = __fmul_rn(__ldg(kp + 4), 2048.0f), kx2 = __fmul_rn(__ldg(kp + 5), 2048.0f);
    float py = __fadd_rn(__fadd_rn(__fmul_rn(b0, ky0), __fmul_rn(b1, ky1)),
                         __fmul_rn(b2, ky2));
    float px = __fadd_rn(__fadd_rn(__fmul_rn(b0, kx0), __fmul_rn(b1, kx1)),
                         __fmul_rn(b2, kx2));

    // Exact point-to-tile-box distance. Squared threshold 4.5 (> 4.0) pads for
    // rounding — only ever KEEPS extra samples (dist(pixel,s) >= boxdist(s)).
    float bdy = fmaxf(fmaxf((float)y0 - py, py - (float)(y0 + TILE_H - 1)), 0.0f);
    float bdx = fmaxf(fmaxf((float)x0 - px, px - (float)(x0 + TILE_W - 1)), 0.0f);
    bool near = (bdy * bdy + bdx * bdx) < 4.5f;
    unsigned mask = __ballot_sync(0xffffffffu, near);

    const int x = x0 + tx * 8;           // 8 consecutive floats = 32B per thread
    float* base = out + (size_t)(y0 + ty) * CANVAS_W + x;

    if (mask == 0u) {
        float z[8] = {0.f, 0.f, 0.f, 0.f, 0.f, 0.f, 0.f, 0.f};
        #pragma unroll
        for (int r = 0; r < ROWS_PER_THREAD; r++)
            stg256(base + (size_t)(r * ROW_STRIDE) * CANVAS_W, z);
    } else {
        const float maxd = sqrtf(2048.0f * 2048.0f + 2048.0f * 2048.0f);
        float fx[8];
        #pragma unroll
        for (int i = 0; i < 8; i++) fx[i] = (float)(x + i);
        #pragma unroll
        for (int r = 0; r < ROWS_PER_THREAD; r++) {
            const float fy = (float)(y0 + ty + r * ROW_STRIDE);
            float m[8];
            #pragma unroll
            for (int i = 0; i < 8; i++) m[i] = 3.4e38f;
            unsigned mm = mask;              // warp-uniform loop
            while (mm) {
                int lane = __ffs(mm) - 1;
                mm &= mm - 1u;
                float syv = __shfl_sync(0xffffffffu, py, lane);
                float sxv = __shfl_sync(0xffffffffu, px, lane);
                float dy  = __fsub_rn(fy, syv);
                float dy2 = __fmul_rn(dy, dy);   // separate op, matches ref
                #pragma unroll
                for (int i = 0; i < 8; i++) {
                    float d = __fsub_rn(fx[i], sxv);
                    m[i] = fminf(m[i], __fadd_rn(dy2, __fmul_rn(d, d)));
                }
            }
            // sqrt BEFORE compare (boundary rounding identical to reference)
            float v[8];
            #pragma unroll
            for (int i = 0; i < 8; i++) {
                float d = sqrtf(m[i]);
                v[i] = (d < 2.0f) ? __fsub_rn(1.0f, __fdiv_rn(d, maxd)) : 0.0f;
            }
            stg256(base + (size_t)(r * ROW_STRIDE) * CANVAS_W, v);
        }
    }
}

extern "C" void kernel_launch(void* const* d_in, const int* in_sizes, int n_in,
                              void* d_out, int out_size)
{
    const float* kp = (const float*)d_in[0];   // [3,2] normalized (y,x)
    float* out = (float*)d_out;                // [2048,2048] fp32

    dim3 block(32, 8);
    dim3 grid(CANVAS_W / TILE_W, CANVAS_H / TILE_H);  // (8, 32) = 256 blocks
    path_raster_kernel<<<grid, block>>>(kp, out);
}

// round 5
// speedup vs baseline: 1.4669x; 1.4669x over previous
#include <cuda_runtime.h>
#include <cuda_bf16.h>

// PathRaster2d R5: memset the canvas (driver fill path, no per-pixel threads),
// then a tiny draw kernel: 32 blocks (one per curve sample) x 64 threads
// (8x8 pixel box around the sample). Each thread computes the FULL 32-sample
// min distance for its pixel (bit-identical arithmetic to rounds 1-4,
// rel_err 0.0) and writes only when dist < LINE_WIDTH. Nonzero pixels are
// always within 2px of their argmin sample => inside that sample's +/-3 box.
// Overlapping boxes write identical full-min values (benign).

#define CANVAS_H 2048
#define CANVAS_W 2048
#define NSAMP 32

__global__ void __launch_bounds__(64)
path_draw_kernel(const float* __restrict__ kp, float* __restrict__ out)
{
    const int lane = threadIdx.x & 31;
    const int tid  = threadIdx.x;        // 0..63
    const int s    = blockIdx.x;         // this block's sample

    // ---- per-lane sample (lane i computes sample i), ref-matched rounding ----
    // t_i = i * fl(1/31), endpoint forced to 1.0 (matches jnp.linspace)
    float t = (lane == 31) ? 1.0f : (float)lane * (1.0f / 31.0f);
    float u = __fsub_rn(1.0f, t);
    float b0 = __fmul_rn(u, u);
    float b1 = __fmul_rn(__fmul_rn(2.0f, t), u);
    float b2 = __fmul_rn(t, t);
    float ky0 = __fmul_rn(__ldg(kp + 0), 2048.0f), kx0 = __fmul_rn(__ldg(kp + 1), 2048.0f);
    float ky1 = __fmul_rn(__ldg(kp + 2), 2048.0f), kx1 = __fmul_rn(__ldg(kp + 3), 2048.0f);
    float ky2 = __fmul_rn(__ldg(kp + 4), 2048.0f), kx2 = __fmul_rn(__ldg(kp + 5), 2048.0f);
    float py = __fadd_rn(__fadd_rn(__fmul_rn(b0, ky0), __fmul_rn(b1, ky1)),
                         __fmul_rn(b2, ky2));
    float px = __fadd_rn(__fadd_rn(__fmul_rn(b0, kx0), __fmul_rn(b1, kx1)),
                         __fmul_rn(b2, kx2));

    // This block's sample point (broadcast from the owning lane)
    float psy = __shfl_sync(0xffffffffu, py, s);
    float psx = __shfl_sync(0xffffffffu, px, s);

    // 8x8 box centered on the sample: covers all pixels within 2px of it.
    const int iy0 = (int)floorf(psy) - 3;
    const int ix0 = (int)floorf(psx) - 3;
    const int yq  = iy0 + (tid >> 3);
    const int xq  = ix0 + (tid & 7);
    if (yq < 0 || yq >= CANVAS_H || xq < 0 || xq >= CANVAS_W) return;

    const float fy = (float)yq;
    const float fx = (float)xq;
    float m = 3.4e38f;
    #pragma unroll
    for (int j = 0; j < NSAMP; j++) {     // full min, sample order 0..31
        float syv = __shfl_sync(0xffffffffu, py, j);
        float sxv = __shfl_sync(0xffffffffu, px, j);
        float dy  = __fsub_rn(fy, syv);
        float dy2 = __fmul_rn(dy, dy);    // separate op, matches reference
        float dx  = __fsub_rn(fx, sxv);
        m = fminf(m, __fadd_rn(dy2, __fmul_rn(dx, dx)));
    }
    // sqrt BEFORE compare (boundary rounding identical to reference)
    float d = sqrtf(m);
    if (d < 2.0f) {
        const float maxd = sqrtf(2048.0f * 2048.0f + 2048.0f * 2048.0f);
        out[(size_t)yq * CANVAS_W + xq] = __fsub_rn(1.0f, __fdiv_rn(d, maxd));
    }
}

extern "C" void kernel_launch(void* const* d_in, const int* in_sizes, int n_in,
                              void* d_out, int out_size)
{
    const float* kp = (const float*)d_in[0];   // [3,2] normalized (y,x)
    float* out = (float*)d_out;                // [2048,2048] fp32

    // Driver fill path for the 99.99%-zero canvas (graph-capturable, no alloc)
    cudaMemsetAsync(d_out, 0, (size_t)CANVAS_H * CANVAS_W * sizeof(float));
    // Draw the curve neighborhood only
    path_draw_kernel<<<NSAMP, 64>>>(kp, out);
}